// round 13
// baseline (speedup 1.0000x reference)
#include <cuda_runtime.h>
#include <math.h>

// Problem constants
#define BB     128
#define TT     512
#define FF     256
#define HH     1024
#define GST    512
#define ITR    512
#define KGC    1280
#define NP     64       // batch pairs (BB/2)

// Launch shape
#define NCTAS  128
#define NTHR   256
#define RG     8        // gate rows per CTA   (1024 / 128)
#define RC     4        // cand rows per CTA   (512 / 128)
#define RH     4        // ghost rows per CTA  (512 / 128)

typedef unsigned long long ull;

// ---------------- device globals (scratch + barrier state) ----------------
// Two independent barrier chains (one per batch half). Arrive-only mutates:
// 1536 arrives per chain per launch (even) -> g_sns ends at 0; g_cnt wraps
// to 0 at every barrier via atomicInc -> replay-safe.
__device__ unsigned g_cnt[2] = {0, 0};
__device__ unsigned g_sns[2] = {0, 0};
// packed x: [t][pair][k][2]  (512*64*512 floats = 67 MB)
__device__ __align__(16) float g_xp[(size_t)TT * NP * 2 * FF];
// packed hidden state ping-pong: [buf][pair][k][2]
__device__ __align__(16) float g_hp[2][NP * 2 * HH];
// packed r*h and u: [pair][n][2]
__device__ __align__(16) float g_rp[NP * 2 * ITR];
__device__ __align__(16) float g_up[NP * 2 * ITR];

// Decoupled arrive / wait (sense-reversing, per-half chain).
// arrive: publish my writes, count in; 128th arriver releases with sense s.
// wait:   poll release word for s. A CTA can only arrive at barrier k+1 of a
// chain after passing wait(k) of that chain, so releases cannot run ahead.
__device__ __forceinline__ void g_arrive(int h, unsigned s) {
    __syncthreads();
    if (threadIdx.x == 0) {
        __threadfence();
        unsigned old = atomicInc(&g_cnt[h], NCTAS - 1u);
        if (old == NCTAS - 1u) atomicExch(&g_sns[h], s);
    }
}
__device__ __forceinline__ void g_wait(int h, unsigned s) {
    if (threadIdx.x == 0) {
        while (((volatile unsigned*)g_sns)[h] != s) { }
        __threadfence();
    }
    __syncthreads();
}

// ---------------- f32x2 packed-math helpers ----------------
__device__ __forceinline__ void ffma2(ull& acc, ull w, ull s) {
    asm("fma.rn.f32x2 %0, %1, %2, %0;" : "+l"(acc) : "l"(w), "l"(s));
}
__device__ __forceinline__ ull addf2(ull a, ull b) {
    ull r; asm("add.rn.f32x2 %0, %1, %2;" : "=l"(r) : "l"(a), "l"(b)); return r;
}
__device__ __forceinline__ ull splat2(float v) {
    ull r; asm("mov.b64 %0, {%1, %1};" : "=l"(r) : "r"(__float_as_uint(v))); return r;
}
__device__ __forceinline__ float f2lo(ull v) { return __uint_as_float((unsigned)v); }
__device__ __forceinline__ float f2hi(ull v) { return __uint_as_float((unsigned)(v >> 32)); }

// 32-value butterfly reduction: lane L ends with cross-lane total of v[L].
__device__ __forceinline__ ull red32u(ull* v, int lane) {
    #pragma unroll
    for (int i = 0; i < 16; ++i) {
        ull a = addf2(v[i],      __shfl_xor_sync(0xffffffffu, v[i],      16));
        ull b = addf2(v[i + 16], __shfl_xor_sync(0xffffffffu, v[i + 16], 16));
        v[i] = (lane & 16) ? b : a;
    }
    #pragma unroll
    for (int i = 0; i < 8; ++i) {
        ull a = addf2(v[i],     __shfl_xor_sync(0xffffffffu, v[i],     8));
        ull b = addf2(v[i + 8], __shfl_xor_sync(0xffffffffu, v[i + 8], 8));
        v[i] = (lane & 8) ? b : a;
    }
    #pragma unroll
    for (int i = 0; i < 4; ++i) {
        ull a = addf2(v[i],     __shfl_xor_sync(0xffffffffu, v[i],     4));
        ull b = addf2(v[i + 4], __shfl_xor_sync(0xffffffffu, v[i + 4], 4));
        v[i] = (lane & 4) ? b : a;
    }
    #pragma unroll
    for (int i = 0; i < 2; ++i) {
        ull a = addf2(v[i],     __shfl_xor_sync(0xffffffffu, v[i],     2));
        ull b = addf2(v[i + 2], __shfl_xor_sync(0xffffffffu, v[i + 2], 2));
        v[i] = (lane & 2) ? b : a;
    }
    {
        ull a = addf2(v[0], __shfl_xor_sync(0xffffffffu, v[0], 1));
        ull b = addf2(v[1], __shfl_xor_sync(0xffffffffu, v[1], 1));
        v[0] = (lane & 1) ? b : a;
    }
    return v[0];
}

// 16-value butterfly reduction: lane L ends with cross-lane total of v[L >> 1].
__device__ __forceinline__ ull red16u(ull* v, int lane) {
    #pragma unroll
    for (int i = 0; i < 8; ++i) {
        ull a = addf2(v[i],     __shfl_xor_sync(0xffffffffu, v[i],     16));
        ull b = addf2(v[i + 8], __shfl_xor_sync(0xffffffffu, v[i + 8], 16));
        v[i] = (lane & 16) ? b : a;
    }
    #pragma unroll
    for (int i = 0; i < 4; ++i) {
        ull a = addf2(v[i],     __shfl_xor_sync(0xffffffffu, v[i],     8));
        ull b = addf2(v[i + 4], __shfl_xor_sync(0xffffffffu, v[i + 4], 8));
        v[i] = (lane & 8) ? b : a;
    }
    #pragma unroll
    for (int i = 0; i < 2; ++i) {
        ull a = addf2(v[i],     __shfl_xor_sync(0xffffffffu, v[i],     4));
        ull b = addf2(v[i + 2], __shfl_xor_sync(0xffffffffu, v[i + 2], 4));
        v[i] = (lane & 4) ? b : a;
    }
    {
        ull a = addf2(v[0], __shfl_xor_sync(0xffffffffu, v[0], 2));
        ull b = addf2(v[1], __shfl_xor_sync(0xffffffffu, v[1], 2));
        v[0] = (lane & 2) ? b : a;
    }
    v[0] = addf2(v[0], __shfl_xor_sync(0xffffffffu, v[0], 1));
    return v[0];
}

// ---------------- pre-pass: pack x and h0 into pair-interleaved layout ----------------
extern "C" __global__ void ghostgru_pack(const float* __restrict__ x,
                                         const float* __restrict__ hid) {
    const size_t nx = (size_t)TT * NP * 2 * FF;
    for (size_t i = (size_t)blockIdx.x * blockDim.x + threadIdx.x; i < nx;
         i += (size_t)gridDim.x * blockDim.x) {
        unsigned h = (unsigned)(i & 1);
        unsigned k = (unsigned)((i >> 1) & (FF - 1));
        unsigned p = (unsigned)((i >> 9) & (NP - 1));
        unsigned t = (unsigned)(i >> 15);
        g_xp[i] = x[((size_t)(2u * p + h) * TT + t) * FF + k];
    }
    const int nh = NP * 2 * HH;
    for (int i = blockIdx.x * blockDim.x + threadIdx.x; i < nh;
         i += gridDim.x * blockDim.x) {
        int h = i & 1;
        int k = (i >> 1) & (HH - 1);
        int p = i >> 11;
        g_hp[0][i] = hid[(2 * p + h) * HH + k];
    }
}

// ---------------- persistent weight-stationary kernel ----------------
extern "C" __global__ void __launch_bounds__(NTHR, 1)
ghostgru_persistent(const float* __restrict__ Wg,    // (1024, 1280)
                    const float* __restrict__ Wc,    // (512, 1280)
                    const float* __restrict__ Wh,    // (512, 512)
                    const float* __restrict__ bg,
                    const float* __restrict__ bc,
                    const float* __restrict__ bh,
                    float*       __restrict__ out,   // (B,T,H) [+ (B,H) tail]
                    int out_size)
{
    extern __shared__ float sm[];
    float* sWg = sm;                        // RG*KGC*2 = 20480 floats (dup pairs)
    float* sWc = sWg + RG * KGC * 2;        // RC*KGC*2 = 10240
    float* sWh = sWc + RC * KGC * 2;        // RH*ITR*2 = 4096
    float* sBg = sWh + RH * ITR * 2;        // RG
    float* sBc = sBg + RG;                  // RC
    float* sBh = sBc + RC;                  // RH

    const int cta  = blockIdx.x;
    const int tid  = threadIdx.x;
    const int wrp  = tid >> 5;
    const int lane = tid & 31;

    // Stage weights duplicated: each scalar w stored as adjacent (w, w).
    for (int i = tid; i < RG * KGC; i += NTHR) {
        float w = Wg[(size_t)cta * (RG * KGC) + i];
        ((float2*)sWg)[i] = make_float2(w, w);
    }
    for (int i = tid; i < RC * KGC; i += NTHR) {
        float w = Wc[(size_t)cta * (RC * KGC) + i];
        ((float2*)sWc)[i] = make_float2(w, w);
    }
    for (int i = tid; i < RH * ITR; i += NTHR) {
        float w = Wh[(size_t)cta * (RH * ITR) + i];
        ((float2*)sWh)[i] = make_float2(w, w);
    }
    if (tid < RG) sBg[tid] = bg[cta * RG + tid];
    if (tid < RC) sBc[tid] = bc[cta * RC + tid];
    if (tid < RH) sBh[tid] = bh[cta * RH + tid];
    __syncthreads();

    const ulonglong2* sWgU = (const ulonglong2*)sWg;   // 640 u2 per row
    const ulonglong2* sWcU = (const ulonglong2*)sWc;   // 640 u2 per row
    const ulonglong2* sWhU = (const ulonglong2*)sWh;   // 256 u2 per row

    const int  ng0  = cta * RG;
    const int  nc0  = cta * RC;
    const int  nh0  = cta * RH;
    const bool is_r = (ng0 < ITR);          // CTAs 0..63 own r rows, 64..127 own u

    unsigned sA = 0, sB = 0;                // per-chain sense trackers

    for (int t = 0; t < TT; ++t) {
        const float* hpc = g_hp[t & 1];
        float*       hpn = g_hp[(t + 1) & 1];
        const float* xrow = g_xp + (size_t)t * (NP * 2 * FF);

        // ================== per-half phase bodies as lambdas ==================
        // half hv: pairs [hv*32, hv*32+32)

        auto phase1 = [&](int hv) {
            const int p0 = hv * 32 + wrp * 4;
            const ulonglong2* xP0 = (const ulonglong2*)(xrow + (size_t)(p0 + 0) * 512);
            const ulonglong2* xP1 = (const ulonglong2*)(xrow + (size_t)(p0 + 1) * 512);
            const ulonglong2* xP2 = (const ulonglong2*)(xrow + (size_t)(p0 + 2) * 512);
            const ulonglong2* xP3 = (const ulonglong2*)(xrow + (size_t)(p0 + 3) * 512);
            const ulonglong2* hP0 = (const ulonglong2*)(hpc + (size_t)(p0 + 0) * 2048);
            const ulonglong2* hP1 = (const ulonglong2*)(hpc + (size_t)(p0 + 1) * 2048);
            const ulonglong2* hP2 = (const ulonglong2*)(hpc + (size_t)(p0 + 2) * 2048);
            const ulonglong2* hP3 = (const ulonglong2*)(hpc + (size_t)(p0 + 3) * 2048);

            ull acc[32];
            #pragma unroll
            for (int i = 0; i < 32; ++i) acc[i] = 0ull;

            #pragma unroll
            for (int it = 0; it < 4; ++it) {            // x segment: u2 [0,128)
                const int off = it * 32 + lane;
                ulonglong2 s0 = __ldcg(xP0 + off);
                ulonglong2 s1 = __ldcg(xP1 + off);
                ulonglong2 s2 = __ldcg(xP2 + off);
                ulonglong2 s3 = __ldcg(xP3 + off);
                #pragma unroll
                for (int j = 0; j < RG; ++j) {
                    ulonglong2 wv = sWgU[j * 640 + off];
                    ffma2(acc[j * 4 + 0], wv.x, s0.x); ffma2(acc[j * 4 + 0], wv.y, s0.y);
                    ffma2(acc[j * 4 + 1], wv.x, s1.x); ffma2(acc[j * 4 + 1], wv.y, s1.y);
                    ffma2(acc[j * 4 + 2], wv.x, s2.x); ffma2(acc[j * 4 + 2], wv.y, s2.y);
                    ffma2(acc[j * 4 + 3], wv.x, s3.x); ffma2(acc[j * 4 + 3], wv.y, s3.y);
                }
            }
            #pragma unroll 4
            for (int it = 0; it < 16; ++it) {           // h segment: u2 [0,512)
                const int off = it * 32 + lane;
                ulonglong2 s0 = __ldcg(hP0 + off);
                ulonglong2 s1 = __ldcg(hP1 + off);
                ulonglong2 s2 = __ldcg(hP2 + off);
                ulonglong2 s3 = __ldcg(hP3 + off);
                #pragma unroll
                for (int j = 0; j < RG; ++j) {
                    ulonglong2 wv = sWgU[j * 640 + 128 + off];
                    ffma2(acc[j * 4 + 0], wv.x, s0.x); ffma2(acc[j * 4 + 0], wv.y, s0.y);
                    ffma2(acc[j * 4 + 1], wv.x, s1.x); ffma2(acc[j * 4 + 1], wv.y, s1.y);
                    ffma2(acc[j * 4 + 2], wv.x, s2.x); ffma2(acc[j * 4 + 2], wv.y, s2.y);
                    ffma2(acc[j * 4 + 3], wv.x, s3.x); ffma2(acc[j * 4 + 3], wv.y, s3.y);
                }
            }

            ull tot = red32u(acc, lane);      // lane L: j = L>>2, pp = L&3
            const int j  = lane >> 2;
            const int pp = lane & 3;
            const int p  = p0 + pp;
            const int n  = ng0 + j;
            ull zb = addf2(tot, splat2(sBg[j]));
            float z0 = f2lo(zb), z1 = f2hi(zb);
            float g0 = 1.0f / (1.0f + __expf(-z0));
            float g1 = 1.0f / (1.0f + __expf(-z1));
            if (is_r) {
                float2 hvv = __ldcg((const float2*)(hpc + (size_t)p * 2048 + (GST + n) * 2));
                *(float2*)(g_rp + (size_t)p * 1024 + n * 2) =
                    make_float2(g0 * hvv.x, g1 * hvv.y);
            } else {
                *(float2*)(g_up + (size_t)p * 1024 + (n - GST) * 2) = make_float2(g0, g1);
            }
        };

        auto phase2 = [&](int hv) {
            const int p0 = hv * 32 + wrp * 4;
            const ulonglong2* xP[4]; const ulonglong2* gP[4]; const ulonglong2* rP[4];
            #pragma unroll
            for (int pp = 0; pp < 4; ++pp) {
                xP[pp] = (const ulonglong2*)(xrow + (size_t)(p0 + pp) * 512);
                gP[pp] = (const ulonglong2*)(hpc + (size_t)(p0 + pp) * 2048);
                rP[pp] = (const ulonglong2*)(g_rp + (size_t)(p0 + pp) * 1024);
            }

            ull acc[16];
            #pragma unroll
            for (int i = 0; i < 16; ++i) acc[i] = 0ull;

            #pragma unroll
            for (int it = 0; it < 4; ++it) {            // x segment
                const int off = it * 32 + lane;
                ulonglong2 sv[4];
                #pragma unroll
                for (int pp = 0; pp < 4; ++pp) sv[pp] = __ldcg(xP[pp] + off);
                #pragma unroll
                for (int j = 0; j < RC; ++j) {
                    ulonglong2 wv = sWcU[j * 640 + off];
                    #pragma unroll
                    for (int pp = 0; pp < 4; ++pp) {
                        ffma2(acc[j * 4 + pp], wv.x, sv[pp].x);
                        ffma2(acc[j * 4 + pp], wv.y, sv[pp].y);
                    }
                }
            }
            #pragma unroll 4
            for (int it = 0; it < 8; ++it) {            // h ghost part: u2 [0,256)
                const int off = it * 32 + lane;
                ulonglong2 sv[4];
                #pragma unroll
                for (int pp = 0; pp < 4; ++pp) sv[pp] = __ldcg(gP[pp] + off);
                #pragma unroll
                for (int j = 0; j < RC; ++j) {
                    ulonglong2 wv = sWcU[j * 640 + 128 + off];
                    #pragma unroll
                    for (int pp = 0; pp < 4; ++pp) {
                        ffma2(acc[j * 4 + pp], wv.x, sv[pp].x);
                        ffma2(acc[j * 4 + pp], wv.y, sv[pp].y);
                    }
                }
            }
            #pragma unroll 4
            for (int it = 0; it < 8; ++it) {            // r_state: u2 [0,256)
                const int off = it * 32 + lane;
                ulonglong2 sv[4];
                #pragma unroll
                for (int pp = 0; pp < 4; ++pp) sv[pp] = __ldcg(rP[pp] + off);
                #pragma unroll
                for (int j = 0; j < RC; ++j) {
                    ulonglong2 wv = sWcU[j * 640 + 384 + off];
                    #pragma unroll
                    for (int pp = 0; pp < 4; ++pp) {
                        ffma2(acc[j * 4 + pp], wv.x, sv[pp].x);
                        ffma2(acc[j * 4 + pp], wv.y, sv[pp].y);
                    }
                }
            }

            ull tot = red16u(acc, lane);      // lane L: idx = L>>1
            if ((lane & 1) == 0) {
                const int idx = lane >> 1;
                const int j  = idx >> 2;
                const int pp = idx & 3;
                const int p  = p0 + pp;
                const int n  = nc0 + j;
                ull zb = addf2(tot, splat2(sBc[j]));
                float c0 = tanhf(f2lo(zb));
                float c1 = tanhf(f2hi(zb));
                float2 uv = __ldcg((const float2*)(g_up + (size_t)p * 1024 + n * 2));
                float2 hvv = __ldcg((const float2*)(hpc + (size_t)p * 2048 + (GST + n) * 2));
                float nh0v = uv.x * hvv.x + (1.0f - uv.x) * c0;
                float nh1v = uv.y * hvv.y + (1.0f - uv.y) * c1;
                out[((size_t)(2 * p + 0) * TT + t) * HH + GST + n] = nh0v;
                out[((size_t)(2 * p + 1) * TT + t) * HH + GST + n] = nh1v;
                *(float2*)(hpn + (size_t)p * 2048 + (GST + n) * 2) =
                    make_float2(nh0v, nh1v);
            }
        };

        auto phase3 = [&](int hv) {
            const int p0 = hv * 32 + wrp * 4;
            const ulonglong2* nP[4];
            #pragma unroll
            for (int pp = 0; pp < 4; ++pp)
                nP[pp] = (const ulonglong2*)(hpn + (size_t)(p0 + pp) * 2048) + 256;

            ull acc[16];
            #pragma unroll
            for (int i = 0; i < 16; ++i) acc[i] = 0ull;

            #pragma unroll 4
            for (int it = 0; it < 8; ++it) {            // new_h (intr part of hpn)
                const int off = it * 32 + lane;
                ulonglong2 sv[4];
                #pragma unroll
                for (int pp = 0; pp < 4; ++pp) sv[pp] = __ldcg(nP[pp] + off);
                #pragma unroll
                for (int j = 0; j < RH; ++j) {
                    ulonglong2 wv = sWhU[j * 256 + off];
                    #pragma unroll
                    for (int pp = 0; pp < 4; ++pp) {
                        ffma2(acc[j * 4 + pp], wv.x, sv[pp].x);
                        ffma2(acc[j * 4 + pp], wv.y, sv[pp].y);
                    }
                }
            }

            ull tot = red16u(acc, lane);
            if ((lane & 1) == 0) {
                const int idx = lane >> 1;
                const int j  = idx >> 2;
                const int pp = idx & 3;
                const int p  = p0 + pp;
                const int n  = nh0 + j;
                ull zb = addf2(tot, splat2(sBh[j]));
                float gh0 = tanhf(f2lo(zb));
                float gh1 = tanhf(f2hi(zb));
                out[((size_t)(2 * p + 0) * TT + t) * HH + n] = gh0;
                out[((size_t)(2 * p + 1) * TT + t) * HH + n] = gh1;
                *(float2*)(hpn + (size_t)p * 2048 + n * 2) = make_float2(gh0, gh1);
            }
        };

        // ============== interleaved schedule: waits hidden behind the other half ==============
        if (t) g_wait(0, sA);           // P3A(t-1) complete across grid
        phase1(0); sA ^= 1u; g_arrive(0, sA);
        if (t) g_wait(1, sB);
        phase1(1); sB ^= 1u; g_arrive(1, sB);

        g_wait(0, sA);                  // P1A complete across grid
        phase2(0); sA ^= 1u; g_arrive(0, sA);
        g_wait(1, sB);
        phase2(1); sB ^= 1u; g_arrive(1, sB);

        g_wait(0, sA);                  // P2A complete across grid
        phase3(0); sA ^= 1u; g_arrive(0, sA);
        g_wait(1, sB);
        phase3(1); sB ^= 1u; g_arrive(1, sB);
        // arrives per chain per step = 3 -> 1536/launch (even): replay-safe.
    }

    // Final grid-wide completion before the tail copy.
    g_wait(0, sA);
    g_wait(1, sB);

    // ---- h_final tail: copy out row (T-1) into the (B, 1, H) region ----
    if (out_size >= (int)((size_t)BB * TT * HH + (size_t)BB * HH)) {
        float* hf = out + (size_t)BB * TT * HH;
        const int total = BB * HH;
        for (int i = cta * NTHR + tid; i < total; i += NCTAS * NTHR) {
            const int b = i / HH;
            const int c = i % HH;
            hf[i] = __ldcg(out + ((size_t)b * TT + (TT - 1)) * HH + c);
        }
    }
}

extern "C" void kernel_launch(void* const* d_in, const int* in_sizes, int n_in,
                              void* d_out, int out_size) {
    const float* x   = (const float*)d_in[0];
    const float* hid = (const float*)d_in[1];
    const float* Wg  = (const float*)d_in[2];
    const float* Wc  = (const float*)d_in[3];
    const float* Wh  = (const float*)d_in[4];
    const float* bg  = (const float*)d_in[5];
    const float* bc  = (const float*)d_in[6];
    const float* bh  = (const float*)d_in[7];
    float* out = (float*)d_out;

    ghostgru_pack<<<2048, 256>>>(x, hid);

    const int smem_bytes = (RG * KGC * 2 + RC * KGC * 2 + RH * ITR * 2
                            + RG + RC + RH) * (int)sizeof(float);   // 139,328 B
    cudaFuncSetAttribute(ghostgru_persistent,
                         cudaFuncAttributeMaxDynamicSharedMemorySize, smem_bytes);

    ghostgru_persistent<<<NCTAS, NTHR, smem_bytes>>>(
        Wg, Wc, Wh, bg, bc, bh, out, out_size);
}

// round 14
// speedup vs baseline: 1.2006x; 1.2006x over previous
#include <cuda_runtime.h>
#include <cuda_bf16.h>
#include <math.h>

// Problem constants
#define BB    128
#define TT    512
#define FF    256
#define HH    1024
#define GST   512
#define ITR   512
#define KGC   1280      // gate/cand reduction dim

// Launch shape: 64 fat CTAs (halves L2 broadcast traffic vs 128)
#define NCTAS 64
#define NTHR  256       // 8 warps; warp w owns batch mtile w (16 rows)

typedef unsigned uint_t;

// ---------------- device globals (scratch + barrier state) ----------------
__device__ unsigned g_bar_count = 0;
__device__ unsigned g_bar_sense = 0;

// Fragment-ready split-bf16 scratches. u32 = 2 bf16 (k, k+1 halves).
// X: [t][mt 8][kt 16][lane 32][reg 4]
__device__ __align__(16) unsigned g_Xh[(size_t)TT * 8 * 16 * 32 * 4];
__device__ __align__(16) unsigned g_Xl[(size_t)TT * 8 * 16 * 32 * 4];
// H ping-pong: [buf 2][mt 8][kt 64][lane][reg]   (h = [ghost | intr], k=1024)
__device__ __align__(16) unsigned g_Hh[2 * 8 * 64 * 32 * 4];
__device__ __align__(16) unsigned g_Hl[2 * 8 * 64 * 32 * 4];
// R (r*h_intr): [mt 8][kt 32][lane][reg]
__device__ __align__(16) unsigned g_Rh[8 * 32 * 32 * 4];
__device__ __align__(16) unsigned g_Rl[8 * 32 * 32 * 4];
// elementwise fp32 scratch
__device__ __align__(16) float g_u[BB * ITR];        // u gate [b][n]
__device__ __align__(16) float g_hf[2][BB * HH];     // fp32 h ping-pong

// Grid-wide sense-reversing barrier (64 CTAs, 1/SM, single wave).
// 1536 barriers/launch (even) -> sense ends 0; count wraps -> replay-safe.
__device__ __forceinline__ void grid_barrier(unsigned sense) {
    __syncthreads();
    if (threadIdx.x == 0) {
        __threadfence();
        unsigned old = atomicInc(&g_bar_count, NCTAS - 1u);
        if (old == NCTAS - 1u) {
            atomicExch(&g_bar_sense, sense);
        } else {
            while (((volatile unsigned*)&g_bar_sense)[0] != sense) { }
        }
        __threadfence();
    }
    __syncthreads();
}

// ---------------- bf16-split helpers ----------------
__device__ __forceinline__ unsigned bfpack(float v0, float v1) {
    unsigned short s0 = __bfloat16_as_ushort(__float2bfloat16(v0));
    unsigned short s1 = __bfloat16_as_ushort(__float2bfloat16(v1));
    return (unsigned)s0 | ((unsigned)s1 << 16);
}
__device__ __forceinline__ float bflo(float v) {
    return v - __bfloat162float(__float2bfloat16(v));
}

// mma.sync m16n8k16 row.col bf16 -> f32
__device__ __forceinline__ void mma_bf16(float* c, uint4 a, unsigned b0, unsigned b1) {
    asm volatile(
        "mma.sync.aligned.m16n8k16.row.col.f32.bf16.bf16.f32 "
        "{%0,%1,%2,%3},{%4,%5,%6,%7},{%8,%9},{%0,%1,%2,%3};"
        : "+f"(c[0]), "+f"(c[1]), "+f"(c[2]), "+f"(c[3])
        : "r"(a.x), "r"(a.y), "r"(a.z), "r"(a.w), "r"(b0), "r"(b1));
}

struct Frag3 { float hh[4], hl[4], lh[4]; };
__device__ __forceinline__ void f3zero(Frag3& f) {
    #pragma unroll
    for (int i = 0; i < 4; ++i) { f.hh[i] = 0.f; f.hl[i] = 0.f; f.lh[i] = 0.f; }
}
// 3-term split accumulation: C += Ah*Bh + Ah*Bl + Al*Bh (independent accs)
__device__ __forceinline__ void mma3(Frag3& f, uint4 Ah, uint4 Al, uint2 Bh, uint2 Bl) {
    mma_bf16(f.hh, Ah, Bh.x, Bh.y);
    mma_bf16(f.hl, Ah, Bl.x, Bl.y);
    mma_bf16(f.lh, Al, Bh.x, Bh.y);
}
__device__ __forceinline__ float f3get(const Frag3& f, int i) {
    return f.hh[i] + f.hl[i] + f.lh[i];
}

// A-fragment u32 index math (value pair at batch-row m, even k-col k0):
//   lane' = (r&7)*4 + ((kk&7)>>1), reg = (r>>3) + ((kk>>3)<<1)
__device__ __forceinline__ int frag_idx(int m, int k0, int kt_dim_unused) {
    int rr = m & 15, kk = k0 & 15;
    return ((rr & 7) * 4 + ((kk & 7) >> 1)) * 4 + (rr >> 3) + ((kk >> 3) << 1);
}

// ---------------- pre-pass: split x (all t) and h0 into fragment scratch ----------------
extern "C" __global__ void gg_pack(const float* __restrict__ x,
                                   const float* __restrict__ hid) {
    const size_t nX = (size_t)TT * 8 * 16 * 32 * 4;
    for (size_t i = (size_t)blockIdx.x * blockDim.x + threadIdx.x; i < nX;
         i += (size_t)gridDim.x * blockDim.x) {
        unsigned reg = (unsigned)i & 3u;
        unsigned lane = (unsigned)(i >> 2) & 31u;
        unsigned kt = (unsigned)(i >> 7) & 15u;
        unsigned mt = (unsigned)(i >> 11) & 7u;
        unsigned t  = (unsigned)(i >> 14);
        int r  = (int)(lane >> 2) + (int)(reg & 1u) * 8;
        int k0 = (int)kt * 16 + (int)(lane & 3u) * 2 + (int)(reg >> 1) * 8;
        int b  = (int)mt * 16 + r;
        float v0 = x[((size_t)b * TT + t) * FF + k0];
        float v1 = x[((size_t)b * TT + t) * FF + k0 + 1];
        g_Xh[i] = bfpack(v0, v1);
        g_Xl[i] = bfpack(bflo(v0), bflo(v1));
    }
    const int nH = 8 * 64 * 32 * 4;     // buf 0 only
    for (int i = blockIdx.x * blockDim.x + threadIdx.x; i < nH;
         i += gridDim.x * blockDim.x) {
        int reg = i & 3, lane = (i >> 2) & 31, kt = (i >> 7) & 63, mt = (i >> 13) & 7;
        int r  = (lane >> 2) + (reg & 1) * 8;
        int k0 = kt * 16 + (lane & 3) * 2 + (reg >> 1) * 8;
        int b  = mt * 16 + r;
        float v0 = hid[b * HH + k0], v1 = hid[b * HH + k0 + 1];
        g_Hh[i] = bfpack(v0, v1);
        g_Hl[i] = bfpack(bflo(v0), bflo(v1));
    }
    for (int i = blockIdx.x * blockDim.x + threadIdx.x; i < BB * HH;
         i += gridDim.x * blockDim.x)
        g_hf[0][i] = hid[i];
}

// ---------------- persistent tensor-core kernel ----------------
extern "C" __global__ void __launch_bounds__(NTHR, 1)
ghostgru_tc(const float* __restrict__ Wg,    // (1024, 1280)
            const float* __restrict__ Wc,    // (512, 1280)
            const float* __restrict__ Wh,    // (512, 512)
            const float* __restrict__ bg,
            const float* __restrict__ bc,
            const float* __restrict__ bh,
            float*       __restrict__ out,   // (B,T,H) [+ (B,H) tail]
            int out_size)
{
    extern __shared__ unsigned smu[];
    unsigned* sWgh = smu;                  // gate B frags hi: [nt2][kt80][lane][reg2]
    unsigned* sWgl = sWgh + 2 * 80 * 64;   // 10240 each
    unsigned* sWch = sWgl + 2 * 80 * 64;   // cand: [kt80][lane][reg2] = 5120
    unsigned* sWcl = sWch + 80 * 64;
    unsigned* sWhh = sWcl + 80 * 64;       // ghost: [kt32][lane][reg2] = 2048
    unsigned* sWhl = sWhh + 32 * 64;
    float* sBg = (float*)(sWhl + 32 * 64); // 16
    float* sBc = sBg + 16;                 // 8
    float* sBh = sBc + 8;                  // 8

    const int cta  = blockIdx.x;
    const int tid  = threadIdx.x;
    const int w    = tid >> 5;             // warp = batch mtile (0..7)
    const int lane = tid & 31;
    const bool is_r = (cta < 32);          // gate rows < 512 are r-gates

    // ---- stage split weights into SMEM in B-fragment order ----
    // gate: positions p = ((nt*80 + kt)*32 + lane)*2 + reg
    for (int p = tid; p < 2 * 80 * 64; p += NTHR) {
        int nt = p / (80 * 64); int rem = p % (80 * 64);
        int kt = rem >> 6; int q = rem & 63; int ln = q >> 1; int rg = q & 1;
        int nrow = cta * 16 + nt * 8 + (ln >> 2);
        int k0 = kt * 16 + (ln & 3) * 2 + rg * 8;
        float v0 = Wg[(size_t)nrow * KGC + k0];
        float v1 = Wg[(size_t)nrow * KGC + k0 + 1];
        sWgh[p] = bfpack(v0, v1);
        sWgl[p] = bfpack(bflo(v0), bflo(v1));
    }
    for (int p = tid; p < 80 * 64; p += NTHR) {
        int kt = p >> 6; int q = p & 63; int ln = q >> 1; int rg = q & 1;
        int nrow = cta * 8 + (ln >> 2);
        int k0 = kt * 16 + (ln & 3) * 2 + rg * 8;
        float v0 = Wc[(size_t)nrow * KGC + k0];
        float v1 = Wc[(size_t)nrow * KGC + k0 + 1];
        sWch[p] = bfpack(v0, v1);
        sWcl[p] = bfpack(bflo(v0), bflo(v1));
    }
    for (int p = tid; p < 32 * 64; p += NTHR) {
        int kt = p >> 6; int q = p & 63; int ln = q >> 1; int rg = q & 1;
        int nrow = cta * 8 + (ln >> 2);
        int k0 = kt * 16 + (ln & 3) * 2 + rg * 8;
        float v0 = Wh[(size_t)nrow * ITR + k0];
        float v1 = Wh[(size_t)nrow * ITR + k0 + 1];
        sWhh[p] = bfpack(v0, v1);
        sWhl[p] = bfpack(bflo(v0), bflo(v1));
    }
    if (tid < 16) sBg[tid] = bg[cta * 16 + tid];
    if (tid < 8)  sBc[tid] = bc[cta * 8 + tid];
    if (tid < 8)  sBh[tid] = bh[cta * 8 + tid];
    __syncthreads();

    const uint2* Bg_h = (const uint2*)sWgh;   // index (nt*80+kt)*32 + lane
    const uint2* Bg_l = (const uint2*)sWgl;
    const uint2* Bc_h = (const uint2*)sWch;   // index kt*32 + lane
    const uint2* Bc_l = (const uint2*)sWcl;
    const uint2* Bh_h = (const uint2*)sWhh;
    const uint2* Bh_l = (const uint2*)sWhl;

    unsigned sense = 0;

    for (int t = 0; t < TT; ++t) {
        const int buf = t & 1, nbuf = (t + 1) & 1;
        const float* hfo = g_hf[buf];
        float*       hfn = g_hf[nbuf];

        const uint4* Xh4 = ((const uint4*)g_Xh) + (((size_t)t * 8 + w) * 16) * 32 + lane;
        const uint4* Xl4 = ((const uint4*)g_Xl) + (((size_t)t * 8 + w) * 16) * 32 + lane;
        const uint4* Hh4 = ((const uint4*)g_Hh) + ((buf * 8 + w) * 64) * 32 + lane;
        const uint4* Hl4 = ((const uint4*)g_Hl) + ((buf * 8 + w) * 64) * 32 + lane;
        const uint4* Rh4 = ((const uint4*)g_Rh) + (w * 32) * 32 + lane;
        const uint4* Rl4 = ((const uint4*)g_Rl) + (w * 32) * 32 + lane;

        // ============ phase 1: gate (C = [x|h] @ Wg^T), 16 rows, 2 ntiles ============
        {
            Frag3 F0, F1; f3zero(F0); f3zero(F1);
            #pragma unroll 4
            for (int kt = 0; kt < 16; ++kt) {           // x segment
                uint4 Ah = __ldg(Xh4 + kt * 32);
                uint4 Al = __ldg(Xl4 + kt * 32);
                uint2 b0h = Bg_h[kt * 32 + lane], b0l = Bg_l[kt * 32 + lane];
                uint2 b1h = Bg_h[(80 + kt) * 32 + lane], b1l = Bg_l[(80 + kt) * 32 + lane];
                mma3(F0, Ah, Al, b0h, b0l);
                mma3(F1, Ah, Al, b1h, b1l);
            }
            #pragma unroll 4
            for (int kt = 0; kt < 64; ++kt) {           // h segment
                uint4 Ah = __ldcg(Hh4 + kt * 32);
                uint4 Al = __ldcg(Hl4 + kt * 32);
                int kg = 16 + kt;
                uint2 b0h = Bg_h[kg * 32 + lane], b0l = Bg_l[kg * 32 + lane];
                uint2 b1h = Bg_h[(80 + kg) * 32 + lane], b1l = Bg_l[(80 + kg) * 32 + lane];
                mma3(F0, Ah, Al, b0h, b0l);
                mma3(F1, Ah, Al, b1h, b1l);
            }
            // epilogue: sigmoid; r-CTAs -> R frags; u-CTAs -> g_u fp32
            #pragma unroll
            for (int nt = 0; nt < 2; ++nt) {
                const Frag3& F = nt ? F1 : F0;
                int nl0 = nt * 8 + 2 * (lane & 3);
                int ng0 = cta * 16 + nl0;               // gate row (even)
                float bia0 = sBg[nl0], bia1 = sBg[nl0 + 1];
                #pragma unroll
                for (int rh = 0; rh < 2; ++rh) {
                    int b = w * 16 + (lane >> 2) + rh * 8;
                    float z0 = f3get(F, rh * 2 + 0) + bia0;
                    float z1 = f3get(F, rh * 2 + 1) + bia1;
                    float s0 = 1.0f / (1.0f + __expf(-z0));
                    float s1 = 1.0f / (1.0f + __expf(-z1));
                    if (is_r) {
                        float2 ho = __ldcg((const float2*)&hfo[b * HH + GST + ng0]);
                        float r0 = s0 * ho.x, r1 = s1 * ho.y;
                        int idx = ((w * 32 + (ng0 >> 4)) * 32) * 4
                                  + frag_idx(b, ng0, 0);
                        g_Rh[idx] = bfpack(r0, r1);
                        g_Rl[idx] = bfpack(bflo(r0), bflo(r1));
                    } else {
                        *(float2*)&g_u[b * ITR + (ng0 - GST)] = make_float2(s0, s1);
                    }
                }
            }
        }
        sense ^= 1u; grid_barrier(sense);

        // ============ phase 2: cand (C = [x|ghost|r] @ Wc^T), 8 rows, 1 ntile ============
        {
            Frag3 F; f3zero(F);
            #pragma unroll 4
            for (int kt = 0; kt < 16; ++kt) {           // x
                uint4 Ah = __ldg(Xh4 + kt * 32);
                uint4 Al = __ldg(Xl4 + kt * 32);
                uint2 bhv = Bc_h[kt * 32 + lane], blv = Bc_l[kt * 32 + lane];
                mma3(F, Ah, Al, bhv, blv);
            }
            #pragma unroll 4
            for (int kt = 0; kt < 32; ++kt) {           // h ghost (h ktiles 0..31)
                uint4 Ah = __ldcg(Hh4 + kt * 32);
                uint4 Al = __ldcg(Hl4 + kt * 32);
                int kg = 16 + kt;
                uint2 bhv = Bc_h[kg * 32 + lane], blv = Bc_l[kg * 32 + lane];
                mma3(F, Ah, Al, bhv, blv);
            }
            #pragma unroll 4
            for (int kt = 0; kt < 32; ++kt) {           // r_state
                uint4 Ah = __ldcg(Rh4 + kt * 32);
                uint4 Al = __ldcg(Rl4 + kt * 32);
                int kg = 48 + kt;
                uint2 bhv = Bc_h[kg * 32 + lane], blv = Bc_l[kg * 32 + lane];
                mma3(F, Ah, Al, bhv, blv);
            }
            // epilogue: tanh, blend with u, write out + hf_new + Hnew intr frags
            int nl0 = 2 * (lane & 3);
            int n0  = cta * 8 + nl0;                    // intr col (even)
            float bia0 = sBc[nl0], bia1 = sBc[nl0 + 1];
            #pragma unroll
            for (int rh = 0; rh < 2; ++rh) {
                int b = w * 16 + (lane >> 2) + rh * 8;
                float c0 = tanhf(f3get(F, rh * 2 + 0) + bia0);
                float c1 = tanhf(f3get(F, rh * 2 + 1) + bia1);
                float2 uv = __ldcg((const float2*)&g_u[b * ITR + n0]);
                float2 ho = __ldcg((const float2*)&hfo[b * HH + GST + n0]);
                float nh0 = uv.x * ho.x + (1.0f - uv.x) * c0;
                float nh1 = uv.y * ho.y + (1.0f - uv.y) * c1;
                *(float2*)&out[((size_t)b * TT + t) * HH + GST + n0] = make_float2(nh0, nh1);
                *(float2*)&hfn[b * HH + GST + n0] = make_float2(nh0, nh1);
                int kcol = GST + n0;
                int idx = (((nbuf * 8 + w) * 64 + (kcol >> 4)) * 32) * 4
                          + frag_idx(b, kcol, 0);
                g_Hh[idx] = bfpack(nh0, nh1);
                g_Hl[idx] = bfpack(bflo(nh0), bflo(nh1));
            }
        }
        sense ^= 1u; grid_barrier(sense);

        // ============ phase 3: ghost (C = new_intr @ Wh^T), 8 rows ============
        {
            const uint4* Nh4 = ((const uint4*)g_Hh) + (((nbuf * 8 + w) * 64 + 32)) * 32 + lane;
            const uint4* Nl4 = ((const uint4*)g_Hl) + (((nbuf * 8 + w) * 64 + 32)) * 32 + lane;
            Frag3 F; f3zero(F);
            #pragma unroll 4
            for (int kt = 0; kt < 32; ++kt) {
                uint4 Ah = __ldcg(Nh4 + kt * 32);
                uint4 Al = __ldcg(Nl4 + kt * 32);
                uint2 bhv = Bh_h[kt * 32 + lane], blv = Bh_l[kt * 32 + lane];
                mma3(F, Ah, Al, bhv, blv);
            }
            int nl0 = 2 * (lane & 3);
            int n0  = cta * 8 + nl0;                    // ghost col (even)
            float bia0 = sBh[nl0], bia1 = sBh[nl0 + 1];
            #pragma unroll
            for (int rh = 0; rh < 2; ++rh) {
                int b = w * 16 + (lane >> 2) + rh * 8;
                float g0 = tanhf(f3get(F, rh * 2 + 0) + bia0);
                float g1 = tanhf(f3get(F, rh * 2 + 1) + bia1);
                *(float2*)&out[((size_t)b * TT + t) * HH + n0] = make_float2(g0, g1);
                *(float2*)&hfn[b * HH + n0] = make_float2(g0, g1);
                int idx = (((nbuf * 8 + w) * 64 + (n0 >> 4)) * 32) * 4
                          + frag_idx(b, n0, 0);
                g_Hh[idx] = bfpack(g0, g1);
                g_Hl[idx] = bfpack(bflo(g0), bflo(g1));
            }
        }
        sense ^= 1u; grid_barrier(sense);
        // 3*512 = 1536 barriers (even): replay-safe.
    }

    // ---- h_final tail: final h lives in g_hf[0] (nbuf at t=511 is 0) ----
    if (out_size >= (int)((size_t)BB * TT * HH + (size_t)BB * HH)) {
        float* hf = out + (size_t)BB * TT * HH;
        for (int i = cta * NTHR + tid; i < BB * HH; i += NCTAS * NTHR)
            hf[i] = __ldcg(&g_hf[0][i]);
    }
}

extern "C" void kernel_launch(void* const* d_in, const int* in_sizes, int n_in,
                              void* d_out, int out_size) {
    const float* x   = (const float*)d_in[0];
    const float* hid = (const float*)d_in[1];
    const float* Wg  = (const float*)d_in[2];
    const float* Wc  = (const float*)d_in[3];
    const float* Wh  = (const float*)d_in[4];
    const float* bg  = (const float*)d_in[5];
    const float* bc  = (const float*)d_in[6];
    const float* bh  = (const float*)d_in[7];
    float* out = (float*)d_out;

    gg_pack<<<2048, 256>>>(x, hid);

    const int smem_bytes = (2 * 80 * 64 * 2 + 80 * 64 * 2 + 32 * 64 * 2) * 4
                           + 32 * 4;                       // 139,392 B
    cudaFuncSetAttribute(ghostgru_tc,
                         cudaFuncAttributeMaxDynamicSharedMemorySize, smem_bytes);

    ghostgru_tc<<<NCTAS, NTHR, smem_bytes>>>(
        Wg, Wc, Wh, bg, bc, bh, out, out_size);
}

// round 15
// speedup vs baseline: 1.3687x; 1.1400x over previous
#include <cuda_runtime.h>
#include <cuda_bf16.h>
#include <math.h>

// Problem constants
#define BB    128
#define TT    512
#define FF    256
#define HH    1024
#define GST   512
#define ITR   512
#define KGC   1280      // gate/cand reduction dim

// Launch shape: 64 fat CTAs, 16 warps each (2 warps cooperate per batch mtile)
#define NCTAS 64
#define NTHR  512

// ---------------- device globals (scratch + barrier state) ----------------
__device__ unsigned g_bar_count = 0;
__device__ unsigned g_bar_sense = 0;

// Fragment-ready split-bf16 scratches. u32 = 2 bf16 (k, k+1 halves).
// X: [t][mt 8][kt 16][lane 32][reg 4]
__device__ __align__(16) unsigned g_Xh[(size_t)TT * 8 * 16 * 32 * 4];
__device__ __align__(16) unsigned g_Xl[(size_t)TT * 8 * 16 * 32 * 4];
// H ping-pong: [buf 2][mt 8][kt 64][lane][reg]   (h = [ghost | intr], k=1024)
__device__ __align__(16) unsigned g_Hh[2 * 8 * 64 * 32 * 4];
__device__ __align__(16) unsigned g_Hl[2 * 8 * 64 * 32 * 4];
// R (r*h_intr): [mt 8][kt 32][lane][reg]
__device__ __align__(16) unsigned g_Rh[8 * 32 * 32 * 4];
__device__ __align__(16) unsigned g_Rl[8 * 32 * 32 * 4];
// elementwise fp32 scratch
__device__ __align__(16) float g_u[BB * ITR];        // u gate [b][n]
__device__ __align__(16) float g_hf[2][BB * HH];     // fp32 h ping-pong

// Grid-wide sense-reversing barrier (64 CTAs, 1/SM, single wave).
// 1536 barriers/launch (even) -> sense ends 0; count wraps -> replay-safe.
__device__ __forceinline__ void grid_barrier(unsigned sense) {
    __syncthreads();
    if (threadIdx.x == 0) {
        __threadfence();
        unsigned old = atomicInc(&g_bar_count, NCTAS - 1u);
        if (old == NCTAS - 1u) {
            atomicExch(&g_bar_sense, sense);
        } else {
            while (((volatile unsigned*)&g_bar_sense)[0] != sense) { }
        }
        __threadfence();
    }
    __syncthreads();
}

// ---------------- bf16-split helpers ----------------
__device__ __forceinline__ unsigned bfpack(float v0, float v1) {
    unsigned short s0 = __bfloat16_as_ushort(__float2bfloat16(v0));
    unsigned short s1 = __bfloat16_as_ushort(__float2bfloat16(v1));
    return (unsigned)s0 | ((unsigned)s1 << 16);
}
__device__ __forceinline__ float bflo(float v) {
    return v - __bfloat162float(__float2bfloat16(v));
}

// mma.sync m16n8k16 row.col bf16 -> f32
__device__ __forceinline__ void mma_bf16(float* c, uint4 a, unsigned b0, unsigned b1) {
    asm volatile(
        "mma.sync.aligned.m16n8k16.row.col.f32.bf16.bf16.f32 "
        "{%0,%1,%2,%3},{%4,%5,%6,%7},{%8,%9},{%0,%1,%2,%3};"
        : "+f"(c[0]), "+f"(c[1]), "+f"(c[2]), "+f"(c[3])
        : "r"(a.x), "r"(a.y), "r"(a.z), "r"(a.w), "r"(b0), "r"(b1));
}

struct Frag3 { float hh[4], hl[4], lh[4]; };
__device__ __forceinline__ void f3zero(Frag3& f) {
    #pragma unroll
    for (int i = 0; i < 4; ++i) { f.hh[i] = 0.f; f.hl[i] = 0.f; f.lh[i] = 0.f; }
}
// 3-term split accumulation: C += Ah*Bh + Ah*Bl + Al*Bh (independent accs)
__device__ __forceinline__ void mma3(Frag3& f, uint4 Ah, uint4 Al, uint2 Bh, uint2 Bl) {
    mma_bf16(f.hh, Ah, Bh.x, Bh.y);
    mma_bf16(f.hl, Ah, Bl.x, Bl.y);
    mma_bf16(f.lh, Al, Bh.x, Bh.y);
}
__device__ __forceinline__ float f3get(const Frag3& f, int i) {
    return f.hh[i] + f.hl[i] + f.lh[i];
}

// A-fragment u32 index math (value pair at batch-row m, even k-col k0)
__device__ __forceinline__ int frag_idx(int m, int k0) {
    int rr = m & 15, kk = k0 & 15;
    return ((rr & 7) * 4 + ((kk & 7) >> 1)) * 4 + (rr >> 3) + ((kk >> 3) << 1);
}

// ---------------- pre-pass: split x (all t) and h0 into fragment scratch ----------------
extern "C" __global__ void gg_pack(const float* __restrict__ x,
                                   const float* __restrict__ hid) {
    const size_t nX = (size_t)TT * 8 * 16 * 32 * 4;
    for (size_t i = (size_t)blockIdx.x * blockDim.x + threadIdx.x; i < nX;
         i += (size_t)gridDim.x * blockDim.x) {
        unsigned reg = (unsigned)i & 3u;
        unsigned lane = (unsigned)(i >> 2) & 31u;
        unsigned kt = (unsigned)(i >> 7) & 15u;
        unsigned mt = (unsigned)(i >> 11) & 7u;
        unsigned t  = (unsigned)(i >> 14);
        int r  = (int)(lane >> 2) + (int)(reg & 1u) * 8;
        int k0 = (int)kt * 16 + (int)(lane & 3u) * 2 + (int)(reg >> 1) * 8;
        int b  = (int)mt * 16 + r;
        float v0 = x[((size_t)b * TT + t) * FF + k0];
        float v1 = x[((size_t)b * TT + t) * FF + k0 + 1];
        g_Xh[i] = bfpack(v0, v1);
        g_Xl[i] = bfpack(bflo(v0), bflo(v1));
    }
    const int nH = 8 * 64 * 32 * 4;     // buf 0 only
    for (int i = blockIdx.x * blockDim.x + threadIdx.x; i < nH;
         i += gridDim.x * blockDim.x) {
        int reg = i & 3, lane = (i >> 2) & 31, kt = (i >> 7) & 63, mt = (i >> 13) & 7;
        int r  = (lane >> 2) + (reg & 1) * 8;
        int k0 = kt * 16 + (lane & 3) * 2 + (reg >> 1) * 8;
        int b  = mt * 16 + r;
        float v0 = hid[b * HH + k0], v1 = hid[b * HH + k0 + 1];
        g_Hh[i] = bfpack(v0, v1);
        g_Hl[i] = bfpack(bflo(v0), bflo(v1));
    }
    for (int i = blockIdx.x * blockDim.x + threadIdx.x; i < BB * HH;
         i += gridDim.x * blockDim.x)
        g_hf[0][i] = hid[i];
}

// ---------------- persistent tensor-core kernel ----------------
extern "C" __global__ void __launch_bounds__(NTHR, 1)
ghostgru_tc(const float* __restrict__ Wg,    // (1024, 1280)
            const float* __restrict__ Wc,    // (512, 1280)
            const float* __restrict__ Wh,    // (512, 512)
            const float* __restrict__ bg,
            const float* __restrict__ bc,
            const float* __restrict__ bh,
            float*       __restrict__ out,   // (B,T,H) [+ (B,H) tail]
            int out_size)
{
    extern __shared__ unsigned smu[];
    unsigned* sWgh = smu;                  // gate B frags hi: [nt2][kt80][lane][reg2]
    unsigned* sWgl = sWgh + 2 * 80 * 64;   // 10240 each
    unsigned* sWch = sWgl + 2 * 80 * 64;   // cand: [kt80][lane][reg2] = 5120
    unsigned* sWcl = sWch + 80 * 64;
    unsigned* sWhh = sWcl + 80 * 64;       // ghost: [kt32][lane][reg2] = 2048
    unsigned* sWhl = sWhh + 32 * 64;
    float* sBg = (float*)(sWhl + 32 * 64); // 16
    float* sBc = sBg + 16;                 // 8
    float* sBh = sBc + 8;                  // 8
    float4* sPart = (float4*)(sBh + 8);    // [16 warps][32 lanes] partial C = 8KB

    const int cta  = blockIdx.x;
    const int tid  = threadIdx.x;
    const int w    = tid >> 5;             // warp 0..15
    const int w2   = w >> 1;               // batch mtile 0..7
    const int half = w & 1;                // pair half
    const int lane = tid & 31;
    const bool is_r = (cta < 32);          // gate rows < 512 are r-gates

    // ---- stage split weights into SMEM in B-fragment order ----
    for (int p = tid; p < 2 * 80 * 64; p += NTHR) {
        int nt = p / (80 * 64); int rem = p % (80 * 64);
        int kt = rem >> 6; int q = rem & 63; int ln = q >> 1; int rg = q & 1;
        int nrow = cta * 16 + nt * 8 + (ln >> 2);
        int k0 = kt * 16 + (ln & 3) * 2 + rg * 8;
        float v0 = Wg[(size_t)nrow * KGC + k0];
        float v1 = Wg[(size_t)nrow * KGC + k0 + 1];
        sWgh[p] = bfpack(v0, v1);
        sWgl[p] = bfpack(bflo(v0), bflo(v1));
    }
    for (int p = tid; p < 80 * 64; p += NTHR) {
        int kt = p >> 6; int q = p & 63; int ln = q >> 1; int rg = q & 1;
        int nrow = cta * 8 + (ln >> 2);
        int k0 = kt * 16 + (ln & 3) * 2 + rg * 8;
        float v0 = Wc[(size_t)nrow * KGC + k0];
        float v1 = Wc[(size_t)nrow * KGC + k0 + 1];
        sWch[p] = bfpack(v0, v1);
        sWcl[p] = bfpack(bflo(v0), bflo(v1));
    }
    for (int p = tid; p < 32 * 64; p += NTHR) {
        int kt = p >> 6; int q = p & 63; int ln = q >> 1; int rg = q & 1;
        int nrow = cta * 8 + (ln >> 2);
        int k0 = kt * 16 + (ln & 3) * 2 + rg * 8;
        float v0 = Wh[(size_t)nrow * ITR + k0];
        float v1 = Wh[(size_t)nrow * ITR + k0 + 1];
        sWhh[p] = bfpack(v0, v1);
        sWhl[p] = bfpack(bflo(v0), bflo(v1));
    }
    if (tid < 16) sBg[tid] = bg[cta * 16 + tid];
    if (tid < 8)  sBc[tid] = bc[cta * 8 + tid];
    if (tid < 8)  sBh[tid] = bh[cta * 8 + tid];
    __syncthreads();

    const uint2* Bg_h = (const uint2*)sWgh;   // index (nt*80+kt)*32 + lane
    const uint2* Bg_l = (const uint2*)sWgl;
    const uint2* Bc_h = (const uint2*)sWch;   // index kt*32 + lane
    const uint2* Bc_l = (const uint2*)sWcl;
    const uint2* Bh_h = (const uint2*)sWhh;
    const uint2* Bh_l = (const uint2*)sWhl;

    unsigned sense = 0;

    for (int t = 0; t < TT; ++t) {
        const int buf = t & 1, nbuf = (t + 1) & 1;
        const float* hfo = g_hf[buf];
        float*       hfn = g_hf[nbuf];

        const uint4* Xh4 = ((const uint4*)g_Xh) + (((size_t)t * 8 + w2) * 16) * 32 + lane;
        const uint4* Xl4 = ((const uint4*)g_Xl) + (((size_t)t * 8 + w2) * 16) * 32 + lane;
        const uint4* Hh4 = ((const uint4*)g_Hh) + ((buf * 8 + w2) * 64) * 32 + lane;
        const uint4* Hl4 = ((const uint4*)g_Hl) + ((buf * 8 + w2) * 64) * 32 + lane;
        const uint4* Rh4 = ((const uint4*)g_Rh) + (w2 * 32) * 32 + lane;
        const uint4* Rl4 = ((const uint4*)g_Rl) + (w2 * 32) * 32 + lane;

        // ============ phase 1: gate. Warp pair splits the 2 n-tiles. ============
        {
            Frag3 F; f3zero(F);
            const int ntb = half * 80;                  // B base for my ntile
            #pragma unroll 4
            for (int kt = 0; kt < 16; ++kt) {           // x segment
                uint4 Ah = __ldg(Xh4 + kt * 32);
                uint4 Al = __ldg(Xl4 + kt * 32);
                uint2 bhv = Bg_h[(ntb + kt) * 32 + lane];
                uint2 blv = Bg_l[(ntb + kt) * 32 + lane];
                mma3(F, Ah, Al, bhv, blv);
            }
            #pragma unroll 4
            for (int kt = 0; kt < 64; ++kt) {           // h segment
                uint4 Ah = __ldcg(Hh4 + kt * 32);
                uint4 Al = __ldcg(Hl4 + kt * 32);
                uint2 bhv = Bg_h[(ntb + 16 + kt) * 32 + lane];
                uint2 blv = Bg_l[(ntb + 16 + kt) * 32 + lane];
                mma3(F, Ah, Al, bhv, blv);
            }
            // epilogue: my ntile = half
            int nl0 = half * 8 + 2 * (lane & 3);
            int ng0 = cta * 16 + nl0;                   // gate row (even)
            float bia0 = sBg[nl0], bia1 = sBg[nl0 + 1];
            #pragma unroll
            for (int rh = 0; rh < 2; ++rh) {
                int b = w2 * 16 + (lane >> 2) + rh * 8;
                float z0 = f3get(F, rh * 2 + 0) + bia0;
                float z1 = f3get(F, rh * 2 + 1) + bia1;
                float s0 = 1.0f / (1.0f + __expf(-z0));
                float s1 = 1.0f / (1.0f + __expf(-z1));
                if (is_r) {
                    float2 ho = __ldcg((const float2*)&hfo[b * HH + GST + ng0]);
                    float r0 = s0 * ho.x, r1 = s1 * ho.y;
                    int idx = ((w2 * 32 + (ng0 >> 4)) * 32) * 4 + frag_idx(b, ng0);
                    g_Rh[idx] = bfpack(r0, r1);
                    g_Rl[idx] = bfpack(bflo(r0), bflo(r1));
                } else {
                    *(float2*)&g_u[b * ITR + (ng0 - GST)] = make_float2(s0, s1);
                }
            }
        }
        sense ^= 1u; grid_barrier(sense);

        // ============ phase 2: cand. Warp pair splits k (40/40 ktiles). ============
        {
            Frag3 F; f3zero(F);
            if (half == 0) {
                #pragma unroll 4
                for (int kt = 0; kt < 16; ++kt) {       // x: logical kt 0..15
                    uint4 Ah = __ldg(Xh4 + kt * 32);
                    uint4 Al = __ldg(Xl4 + kt * 32);
                    uint2 bhv = Bc_h[kt * 32 + lane], blv = Bc_l[kt * 32 + lane];
                    mma3(F, Ah, Al, bhv, blv);
                }
                #pragma unroll 4
                for (int kt = 0; kt < 24; ++kt) {       // ghost: logical 16..39
                    uint4 Ah = __ldcg(Hh4 + kt * 32);
                    uint4 Al = __ldcg(Hl4 + kt * 32);
                    uint2 bhv = Bc_h[(16 + kt) * 32 + lane];
                    uint2 blv = Bc_l[(16 + kt) * 32 + lane];
                    mma3(F, Ah, Al, bhv, blv);
                }
            } else {
                #pragma unroll 4
                for (int kt = 24; kt < 32; ++kt) {      // ghost: logical 40..47
                    uint4 Ah = __ldcg(Hh4 + kt * 32);
                    uint4 Al = __ldcg(Hl4 + kt * 32);
                    uint2 bhv = Bc_h[(16 + kt) * 32 + lane];
                    uint2 blv = Bc_l[(16 + kt) * 32 + lane];
                    mma3(F, Ah, Al, bhv, blv);
                }
                #pragma unroll 4
                for (int kt = 0; kt < 32; ++kt) {       // r_state: logical 48..79
                    uint4 Ah = __ldcg(Rh4 + kt * 32);
                    uint4 Al = __ldcg(Rl4 + kt * 32);
                    uint2 bhv = Bc_h[(48 + kt) * 32 + lane];
                    uint2 blv = Bc_l[(48 + kt) * 32 + lane];
                    mma3(F, Ah, Al, bhv, blv);
                }
            }
            // cross-warp-pair reduction via SMEM
            sPart[w * 32 + lane] = make_float4(f3get(F, 0), f3get(F, 1),
                                               f3get(F, 2), f3get(F, 3));
            __syncthreads();
            float4 pa = sPart[(w2 * 2 + 0) * 32 + lane];
            float4 pb = sPart[(w2 * 2 + 1) * 32 + lane];
            // this warp handles row-half rh = half
            float c0v = half ? (pa.z + pb.z) : (pa.x + pb.x);
            float c1v = half ? (pa.w + pb.w) : (pa.y + pb.y);
            int nl0 = 2 * (lane & 3);
            int n0  = cta * 8 + nl0;                    // intr col (even)
            float c0 = tanhf(c0v + sBc[nl0]);
            float c1 = tanhf(c1v + sBc[nl0 + 1]);
            int b = w2 * 16 + (lane >> 2) + half * 8;
            float2 uv = __ldcg((const float2*)&g_u[b * ITR + n0]);
            float2 ho = __ldcg((const float2*)&hfo[b * HH + GST + n0]);
            float nh0 = uv.x * ho.x + (1.0f - uv.x) * c0;
            float nh1 = uv.y * ho.y + (1.0f - uv.y) * c1;
            *(float2*)&out[((size_t)b * TT + t) * HH + GST + n0] = make_float2(nh0, nh1);
            *(float2*)&hfn[b * HH + GST + n0] = make_float2(nh0, nh1);
            int kcol = GST + n0;
            int idx = (((nbuf * 8 + w2) * 64 + (kcol >> 4)) * 32) * 4 + frag_idx(b, kcol);
            g_Hh[idx] = bfpack(nh0, nh1);
            g_Hl[idx] = bfpack(bflo(nh0), bflo(nh1));
        }
        sense ^= 1u; grid_barrier(sense);

        // ============ phase 3: ghost. Warp pair splits k (16/16 ktiles). ============
        {
            const uint4* Nh4 = ((const uint4*)g_Hh)
                               + ((nbuf * 8 + w2) * 64 + 32 + half * 16) * 32 + lane;
            const uint4* Nl4 = ((const uint4*)g_Hl)
                               + ((nbuf * 8 + w2) * 64 + 32 + half * 16) * 32 + lane;
            Frag3 F; f3zero(F);
            #pragma unroll 4
            for (int kt = 0; kt < 16; ++kt) {
                uint4 Ah = __ldcg(Nh4 + kt * 32);
                uint4 Al = __ldcg(Nl4 + kt * 32);
                uint2 bhv = Bh_h[(half * 16 + kt) * 32 + lane];
                uint2 blv = Bh_l[(half * 16 + kt) * 32 + lane];
                mma3(F, Ah, Al, bhv, blv);
            }
            sPart[w * 32 + lane] = make_float4(f3get(F, 0), f3get(F, 1),
                                               f3get(F, 2), f3get(F, 3));
            __syncthreads();
            float4 pa = sPart[(w2 * 2 + 0) * 32 + lane];
            float4 pb = sPart[(w2 * 2 + 1) * 32 + lane];
            float c0v = half ? (pa.z + pb.z) : (pa.x + pb.x);
            float c1v = half ? (pa.w + pb.w) : (pa.y + pb.y);
            int nl0 = 2 * (lane & 3);
            int n0  = cta * 8 + nl0;                    // ghost col (even)
            float g0 = tanhf(c0v + sBh[nl0]);
            float g1 = tanhf(c1v + sBh[nl0 + 1]);
            int b = w2 * 16 + (lane >> 2) + half * 8;
            *(float2*)&out[((size_t)b * TT + t) * HH + n0] = make_float2(g0, g1);
            *(float2*)&hfn[b * HH + n0] = make_float2(g0, g1);
            int idx = (((nbuf * 8 + w2) * 64 + (n0 >> 4)) * 32) * 4 + frag_idx(b, n0);
            g_Hh[idx] = bfpack(g0, g1);
            g_Hl[idx] = bfpack(bflo(g0), bflo(g1));
        }
        sense ^= 1u; grid_barrier(sense);
        // 3*512 = 1536 barriers (even): replay-safe.
    }

    // ---- h_final tail: final h lives in g_hf[0] (nbuf at t=511 is 0) ----
    if (out_size >= (int)((size_t)BB * TT * HH + (size_t)BB * HH)) {
        float* hf = out + (size_t)BB * TT * HH;
        for (int i = cta * NTHR + tid; i < BB * HH; i += NCTAS * NTHR)
            hf[i] = __ldcg(&g_hf[0][i]);
    }
}

extern "C" void kernel_launch(void* const* d_in, const int* in_sizes, int n_in,
                              void* d_out, int out_size) {
    const float* x   = (const float*)d_in[0];
    const float* hid = (const float*)d_in[1];
    const float* Wg  = (const float*)d_in[2];
    const float* Wc  = (const float*)d_in[3];
    const float* Wh  = (const float*)d_in[4];
    const float* bg  = (const float*)d_in[5];
    const float* bc  = (const float*)d_in[6];
    const float* bh  = (const float*)d_in[7];
    float* out = (float*)d_out;

    gg_pack<<<2048, 256>>>(x, hid);

    const int smem_bytes = (2 * 80 * 64 * 2 + 80 * 64 * 2 + 32 * 64 * 2) * 4
                           + 32 * 4 + 16 * 32 * 16;        // 147,712 B
    cudaFuncSetAttribute(ghostgru_tc,
                         cudaFuncAttributeMaxDynamicSharedMemorySize, smem_bytes);

    ghostgru_tc<<<NCTAS, NTHR, smem_bytes>>>(
        Wg, Wc, Wh, bg, bc, bh, out, out_size);
}